// round 15
// baseline (speedup 1.0000x reference)
#include <cuda_runtime.h>
#include <cuda_bf16.h>
#include <cstdint>
#include <cstddef>

// ============================================================================
// DecagonModel — R15: R14 + batched preprocessing launches (15 wt_t -> 3,
// 25 CSR-build -> 5) + BK=64 GEMM chunks (half the sync overhead).
// ============================================================================

#define KN0 30000
#define KN1 6000
#define KF  1024
#define KH  512
#define LDO 1536
#define ECAP 2100000
#define RPN  30001

// ---------------- device-global scratch -------------------------------------
__device__ float g_tmpA[KN0 * 1024];
__device__ float g_tmpB[KN1 * 1536];

__device__ float g_f0t[KN0 * KF];
__device__ float g_f1t[KN1 * KF];
__device__ float g_e00t[KN0 * KH];
__device__ float g_e01t[KN1 * KH];
__device__ float g_e20t[KN0 * KH];
__device__ float g_e21t[KN1 * KH];

#define WT_TOTAL 5242880
__device__ float g_wt[WT_TOTAL];

__device__ int   g_rp[5 * RPN];
__device__ int   g_wp[5 * RPN];
__device__ int   g_colv[ECAP];
__device__ float g_valv[ECAP];

// ---------------- helpers ---------------------------------------------------
__device__ __forceinline__ uint32_t smem_u32(const void* p) {
    uint32_t a;
    asm("{ .reg .u64 t; cvta.to.shared.u64 t, %1; cvt.u32.u64 %0, t; }"
        : "=r"(a) : "l"(p));
    return a;
}
__device__ __forceinline__ void cpa16(uint32_t dst, const void* src, bool v) {
    asm volatile("cp.async.cg.shared.global [%0], [%1], 16, %2;"
                 :: "r"(dst), "l"(src), "r"(v ? 16 : 0) : "memory");
}
__device__ __forceinline__ void ldsm4(uint32_t& r0, uint32_t& r1, uint32_t& r2,
                                      uint32_t& r3, uint32_t addr) {
    asm volatile("ldmatrix.sync.aligned.m8n8.x4.shared.b16 {%0,%1,%2,%3}, [%4];"
                 : "=r"(r0), "=r"(r1), "=r"(r2), "=r"(r3) : "r"(addr));
}
__device__ __forceinline__ void mma_tf32(float& c0, float& c1, float& c2, float& c3,
                                         uint32_t a0, uint32_t a1, uint32_t a2, uint32_t a3,
                                         uint32_t b0, uint32_t b1) {
    asm volatile(
        "mma.sync.aligned.m16n8k8.row.col.f32.tf32.tf32.f32 "
        "{%0,%1,%2,%3}, {%4,%5,%6,%7}, {%8,%9}, {%0,%1,%2,%3};"
        : "+f"(c0), "+f"(c1), "+f"(c2), "+f"(c3)
        : "r"(a0), "r"(a1), "r"(a2), "r"(a3), "r"(b0), "r"(b1));
}
__device__ __forceinline__ float tf32r(float x) {
    uint32_t r;
    asm("cvt.rna.tf32.f32 %0, %1;" : "=r"(r) : "f"(x));
    return __uint_as_float(r);
}

// ----------------------------------------------------------------------------
// TF32 GEMM: C[M,N] = A[M,K] @ B^T (B stored [N,K]).  grid (N/128, ceil(M/128)).
// CTA 128x128, BK=64 (two 32KB sub-chunks), 3-stage cp.async, 256 threads.
// Fragment double-buffering across the 8 k8 steps per chunk.
// ----------------------------------------------------------------------------
#define STG_BYTES 65536u                 // sub0{A16K|B16K} sub1{A16K|B16K}
#define GEMM_SMEM (3 * STG_BYTES)        // 192 KB -> 1 CTA/SM

__global__ __launch_bounds__(256) void gemm_tf32(
    const float* __restrict__ A, const float* __restrict__ B,
    float* __restrict__ C, int M, int N, int K)
{
    extern __shared__ char dyn_smem[];
    const uint32_t sbase = smem_u32(dyn_smem);

    const int tid  = threadIdx.x;
    const int wid  = tid >> 5;
    const int lane = tid & 31;
    const int bm   = blockIdx.y * 128;
    const int bn   = blockIdx.x * 128;
    const int wm   = (wid & 1) * 64;
    const int wn   = (wid >> 1) * 32;

    const int NC = K >> 6;               // 64-float chunks

    const int r0 = tid >> 3, cs = tid & 7;
    const uint32_t d0 = (uint32_t)(r0 * 128 + ((cs * 16) ^ ((r0 & 7) << 4)));
    const float* pA[4]; const float* pB[4]; bool vA[4];
#pragma unroll
    for (int it = 0; it < 4; it++) {
        int r  = r0 + 32 * it;
        int gr = bm + r;
        vA[it] = gr < M;
        pA[it] = A + (size_t)(vA[it] ? gr : 0) * K + cs * 4;
        pB[it] = B + (size_t)(bn + r) * K + cs * 4;
    }

    const int mi  = lane >> 3;
    const int r8  = lane & 7;
    const int aro = (mi & 1) * 8 + r8;
    const int akb = (mi >> 1) * 16;
    uint32_t offA[4], offB[2];
#pragma unroll
    for (int i = 0; i < 4; i++) {
        int r = wm + i * 16 + aro;
        offA[i] = (uint32_t)(r * 128 + (akb ^ ((r & 7) << 4)));
    }
#pragma unroll
    for (int j2 = 0; j2 < 2; j2++) {
        int r = wn + j2 * 16 + aro;
        offB[j2] = (uint32_t)(16384 + r * 128 + (akb ^ ((r & 7) << 4)));
    }

    float acc[4][4][4];
#pragma unroll
    for (int i = 0; i < 4; i++)
#pragma unroll
        for (int j = 0; j < 4; j++)
#pragma unroll
            for (int q = 0; q < 4; q++) acc[i][j][q] = 0.f;

    auto load_chunk = [&](uint32_t stW) {
#pragma unroll
        for (int sub = 0; sub < 2; sub++) {
            const uint32_t dA = sbase + stW + (uint32_t)sub * 32768u + d0;
#pragma unroll
            for (int it = 0; it < 4; it++) {
                cpa16(dA + 4096u * it,          pA[it], vA[it]);
                cpa16(dA + 16384u + 4096u * it, pB[it], true);
                pA[it] += 32; pB[it] += 32;
            }
        }
        asm volatile("cp.async.commit_group;" ::: "memory");
    };

    uint32_t stW = 0, stR = 0;
    load_chunk(stW); stW = STG_BYTES;
    load_chunk(stW); stW = 2 * STG_BYTES;

    uint32_t fa[2][4][4], fb[2][4][2];

    auto load_frags = [&](uint32_t base, uint32_t kb, int buf) {
#pragma unroll
        for (int i = 0; i < 4; i++)
            ldsm4(fa[buf][i][0], fa[buf][i][1], fa[buf][i][2], fa[buf][i][3],
                  base + (offA[i] ^ kb));
#pragma unroll
        for (int j2 = 0; j2 < 2; j2++) {
            uint32_t q0, q1, q2, q3;
            ldsm4(q0, q1, q2, q3, base + (offB[j2] ^ kb));
            fb[buf][j2 * 2][0]     = q0; fb[buf][j2 * 2][1]     = q2;
            fb[buf][j2 * 2 + 1][0] = q1; fb[buf][j2 * 2 + 1][1] = q3;
        }
    };
    auto do_mmas = [&](int buf) {
#pragma unroll
        for (int i = 0; i < 4; i++)
#pragma unroll
            for (int j = 0; j < 4; j++)
                mma_tf32(acc[i][j][0], acc[i][j][1], acc[i][j][2], acc[i][j][3],
                         fa[buf][i][0], fa[buf][i][1], fa[buf][i][2], fa[buf][i][3],
                         fb[buf][j][0], fb[buf][j][1]);
    };

    for (int c = 0; c < NC; c++) {
        asm volatile("cp.async.wait_group 1;" ::: "memory");
        __syncthreads();
        if (c + 2 < NC) {
            load_chunk(stW);
            stW += STG_BYTES; if (stW == 3 * STG_BYTES) stW = 0;
        }

        const uint32_t st = sbase + stR;
        stR += STG_BYTES; if (stR == 3 * STG_BYTES) stR = 0;

        load_frags(st, 0, 0);
#pragma unroll
        for (int s = 0; s < 8; s++) {
            if (s < 7) {
                int ns = s + 1;
                load_frags(st + (uint32_t)((ns >> 2) * 32768),
                           (uint32_t)(32 * (ns & 3)), ns & 1);
            }
            do_mmas(s & 1);
        }
    }

    const int lm = lane >> 2, ln = (lane & 3) * 2;
#pragma unroll
    for (int i = 0; i < 4; i++) {
#pragma unroll
        for (int j = 0; j < 4; j++) {
            int m0 = bm + wm + i * 16 + lm;
            int n0 = bn + wn + j * 8 + ln;
            if (m0 < M)
                *(float2*)(C + (size_t)m0 * N + n0) =
                    make_float2(acc[i][j][0], acc[i][j][1]);
            if (m0 + 8 < M)
                *(float2*)(C + (size_t)(m0 + 8) * N + n0) =
                    make_float2(acc[i][j][2], acc[i][j][3]);
        }
    }
}

// ----------------------------------------------------------------------------
// Batched CSR build
// ----------------------------------------------------------------------------
struct CsrArgs {
    const int*   row[5];
    const int*   col[5];
    const float* val[5];
    int          E[5];
    long long    eoff[5];
};

__global__ void seti(int* __restrict__ p, int n, int v)
{
    int i = blockIdx.x * blockDim.x + threadIdx.x;
    if (i < n) p[i] = v;
}
__global__ void hist_b(CsrArgs a, int* __restrict__ wp)
{
    int z = blockIdx.z;
    int i = blockIdx.x * blockDim.x + threadIdx.x;
    if (i < a.E[z]) atomicAdd(&wp[z * RPN + a.row[z][i]], 1);
}
// 5 blocks; block z scans relation z's counts into rowptr
__global__ void exscan_b(const int* __restrict__ cnt_all, int* __restrict__ rp_all)
{
    __shared__ int part[1024];
    const int z = blockIdx.x;
    const int n = (z < 2) ? KN0 : KN1;
    const int* cnt = cnt_all + z * RPN;
    int* rp = rp_all + z * RPN;
    const int t = threadIdx.x;
    const int chunk = (n + 1 + 1023) / 1024;
    const int base = t * chunk;
    int s = 0;
    for (int i = 0; i < chunk; i++) {
        int idx = base + i;
        if (idx < n) s += cnt[idx];
    }
    part[t] = s;
    __syncthreads();
    for (int off = 1; off < 1024; off <<= 1) {
        int v = (t >= off) ? part[t - off] : 0;
        __syncthreads();
        part[t] += v;
        __syncthreads();
    }
    int run = part[t] - s;
    for (int i = 0; i < chunk; i++) {
        int idx = base + i;
        if (idx <= n) {
            rp[idx] = run;
            if (idx < n) run += cnt[idx];
        }
    }
}
__global__ void copyi(const int* __restrict__ s, int* __restrict__ d, int n)
{
    int i = blockIdx.x * blockDim.x + threadIdx.x;
    if (i < n) d[i] = s[i];
}
__global__ void scatter_b(CsrArgs a, int* __restrict__ wp,
                          int* __restrict__ colv, float* __restrict__ valv)
{
    int z = blockIdx.z;
    int i = blockIdx.x * blockDim.x + threadIdx.x;
    if (i >= a.E[z]) return;
    int p = atomicAdd(&wp[z * RPN + a.row[z][i]], 1);
    colv[a.eoff[z] + p] = a.col[z][i];
    valv[a.eoff[z] + p] = a.val[z][i];
}

// ----------------------------------------------------------------------------
// Multi-relation SpMM (unchanged from R14)
// ----------------------------------------------------------------------------
struct RelSrc {
    const int*   rp;
    const int*   colv;
    const float* valv;
    const float* x;
    int          ldx;
};

__device__ __forceinline__ void spmm_acc(
    const RelSrc& R, int row, int lane,
    float4& a0, float4& a1, float4& a2, float4& a3)
{
    int s = __ldg(&R.rp[row]), e = __ldg(&R.rp[row + 1]);
#pragma unroll 2
    for (int i = s; i < e; i++) {
        int   c = __ldg(&R.colv[i]);
        float v = __ldg(&R.valv[i]);
        const float4* xr = reinterpret_cast<const float4*>(R.x + (size_t)c * R.ldx);
        float4 t;
        t = xr[lane];
        a0.x = fmaf(v, t.x, a0.x); a0.y = fmaf(v, t.y, a0.y);
        a0.z = fmaf(v, t.z, a0.z); a0.w = fmaf(v, t.w, a0.w);
        t = xr[lane + 32];
        a1.x = fmaf(v, t.x, a1.x); a1.y = fmaf(v, t.y, a1.y);
        a1.z = fmaf(v, t.z, a1.z); a1.w = fmaf(v, t.w, a1.w);
        t = xr[lane + 64];
        a2.x = fmaf(v, t.x, a2.x); a2.y = fmaf(v, t.y, a2.y);
        a2.z = fmaf(v, t.z, a2.z); a2.w = fmaf(v, t.w, a2.w);
        t = xr[lane + 96];
        a3.x = fmaf(v, t.x, a3.x); a3.y = fmaf(v, t.y, a3.y);
        a3.z = fmaf(v, t.z, a3.z); a3.w = fmaf(v, t.w, a3.w);
    }
}

template <int MODE, int NREL>
__global__ __launch_bounds__(256) void spmm_multi(
    RelSrc r0, RelSrc r1, RelSrc r2,
    float* __restrict__ dst, float* __restrict__ out2, int nrows, int ldo)
{
    int row  = (blockIdx.x * blockDim.x + threadIdx.x) >> 5;
    int lane = threadIdx.x & 31;
    if (row >= nrows) return;

    float4 a0 = make_float4(0.f, 0.f, 0.f, 0.f), a1 = a0, a2 = a0, a3 = a0;
    spmm_acc(r0, row, lane, a0, a1, a2, a3);
    if (NREL >= 2) spmm_acc(r1, row, lane, a0, a1, a2, a3);
    if (NREL >= 3) spmm_acc(r2, row, lane, a0, a1, a2, a3);

    if (MODE == 0) {
        float4* o = reinterpret_cast<float4*>(dst + (size_t)row * ldo);
        o[lane] = a0; o[lane + 32] = a1; o[lane + 64] = a2; o[lane + 96] = a3;
        return;
    }

    a0.x = fmaxf(a0.x, 0.f); a0.y = fmaxf(a0.y, 0.f); a0.z = fmaxf(a0.z, 0.f); a0.w = fmaxf(a0.w, 0.f);
    a1.x = fmaxf(a1.x, 0.f); a1.y = fmaxf(a1.y, 0.f); a1.z = fmaxf(a1.z, 0.f); a1.w = fmaxf(a1.w, 0.f);
    a2.x = fmaxf(a2.x, 0.f); a2.y = fmaxf(a2.y, 0.f); a2.z = fmaxf(a2.z, 0.f); a2.w = fmaxf(a2.w, 0.f);
    a3.x = fmaxf(a3.x, 0.f); a3.y = fmaxf(a3.y, 0.f); a3.z = fmaxf(a3.z, 0.f); a3.w = fmaxf(a3.w, 0.f);

    if (MODE == 1) {
        float4* o = reinterpret_cast<float4*>(out2 + (size_t)row * LDO);
        o[lane]       = a0; o[lane + 32]  = a1; o[lane + 64]  = a2; o[lane + 96]  = a3;
        o[lane + 128] = a0; o[lane + 160] = a1; o[lane + 192] = a2; o[lane + 224] = a3;
    }

    a0.x = tf32r(a0.x); a0.y = tf32r(a0.y); a0.z = tf32r(a0.z); a0.w = tf32r(a0.w);
    a1.x = tf32r(a1.x); a1.y = tf32r(a1.y); a1.z = tf32r(a1.z); a1.w = tf32r(a1.w);
    a2.x = tf32r(a2.x); a2.y = tf32r(a2.y); a2.z = tf32r(a2.z); a2.w = tf32r(a2.w);
    a3.x = tf32r(a3.x); a3.y = tf32r(a3.y); a3.z = tf32r(a3.z); a3.w = tf32r(a3.w);
    float4* p = reinterpret_cast<float4*>(dst + (size_t)row * KH);
    p[lane] = a0; p[lane + 32] = a1; p[lane + 64] = a2; p[lane + 96] = a3;
}

// ----------------------------------------------------------------------------
// Converters (batched weight transpose+round: one launch per layer)
// ----------------------------------------------------------------------------
__global__ void tf32_round4(const float* __restrict__ x, float* __restrict__ y, size_t n4)
{
    size_t i = blockIdx.x * (size_t)blockDim.x + threadIdx.x;
    if (i >= n4) return;
    float4 t = reinterpret_cast<const float4*>(x)[i];
    t.x = tf32r(t.x); t.y = tf32r(t.y); t.z = tf32r(t.z); t.w = tf32r(t.w);
    reinterpret_cast<float4*>(y)[i] = t;
}

struct WtArgs { const float* W[5]; float* T[5]; };

__global__ void wt_batch(WtArgs a, int K)
{
    const int z = blockIdx.z;
    const float* W = a.W[z];
    float* T = a.T[z];
    __shared__ float t[32][33];
    int kb = blockIdx.x * 32, nb = blockIdx.y * 32;
    int x = threadIdx.x, y = threadIdx.y;
#pragma unroll
    for (int i = 0; i < 32; i += 8)
        t[y + i][x] = W[(size_t)(kb + y + i) * KH + nb + x];
    __syncthreads();
#pragma unroll
    for (int i = 0; i < 32; i += 8)
        T[(size_t)(nb + y + i) * K + kb + x] = tf32r(t[x][y + i]);
}

// ----------------------------------------------------------------------------
// Host orchestration
// ----------------------------------------------------------------------------
extern "C" void kernel_launch(void* const* d_in, const int* in_sizes, int n_in,
                              void* d_out, int out_size)
{
    const float* feat0 = (const float*)d_in[0];
    const float* feat1 = (const float*)d_in[1];

    const int*   a_row[5]; const int* a_col[5]; const float* a_val[5]; int Ecnt[5];
    for (int i = 0; i < 5; i++) {
        a_row[i] = (const int*)d_in[2 + 3 * i];
        a_col[i] = (const int*)d_in[3 + 3 * i];
        a_val[i] = (const float*)d_in[4 + 3 * i];
        Ecnt[i]  = in_sizes[2 + 3 * i];
    }
    const float* W[3][5];
    for (int r = 0; r < 5; r++)
        for (int l = 0; l < 3; l++)
            W[l][r] = (const float*)d_in[17 + 3 * r + l];

    float *tmpA, *tmpB;
    float *f0t, *f1t, *e00t, *e01t, *e20t, *e21t, *wt;
    int *rp, *wp, *colv; float *valv;
    {
        void* p;
        cudaGetSymbolAddress(&p, g_tmpA); tmpA = (float*)p;
        cudaGetSymbolAddress(&p, g_tmpB); tmpB = (float*)p;
        cudaGetSymbolAddress(&p, g_f0t);  f0t  = (float*)p;
        cudaGetSymbolAddress(&p, g_f1t);  f1t  = (float*)p;
        cudaGetSymbolAddress(&p, g_e00t); e00t = (float*)p;
        cudaGetSymbolAddress(&p, g_e01t); e01t = (float*)p;
        cudaGetSymbolAddress(&p, g_e20t); e20t = (float*)p;
        cudaGetSymbolAddress(&p, g_e21t); e21t = (float*)p;
        cudaGetSymbolAddress(&p, g_wt);   wt   = (float*)p;
        cudaGetSymbolAddress(&p, g_rp);   rp   = (int*)p;
        cudaGetSymbolAddress(&p, g_wp);   wp   = (int*)p;
        cudaGetSymbolAddress(&p, g_colv); colv = (int*)p;
        cudaGetSymbolAddress(&p, g_valv); valv = (float*)p;
    }
    float* out = (float*)d_out;

    const size_t WA_off[3] = {0, 2621440, 3932160};
    const size_t WB_off[3] = {1048576, 3145728, 4456448};
    const int    Kl[3]     = {KF, KH, KH};

    size_t eoff[5]; size_t acc_e = 0;
    for (int r = 0; r < 5; r++) { eoff[r] = acc_e; acc_e += (size_t)Ecnt[r]; }
    int maxE = 0;
    for (int r = 0; r < 5; r++) if (Ecnt[r] > maxE) maxE = Ecnt[r];

    cudaFuncSetAttribute(gemm_tf32, cudaFuncAttributeMaxDynamicSharedMemorySize, GEMM_SMEM);

    auto gemm = [&](const float* A, const float* B, float* C, int M, int N, int K) {
        dim3 grid(N / 128, (M + 127) / 128);
        gemm_tf32<<<grid, 256, GEMM_SMEM>>>(A, B, C, M, N, K);
    };
    auto wt_layer = [&](int l) {
        int K = Kl[l];
        WtArgs a;
        // relation -> fused block slot: rel0->wA rows 0, rel2->wA rows 512,
        // rel1->wB rows 0, rel3->wB rows 512, rel4->wB rows 1024
        a.W[0] = W[l][0]; a.T[0] = wt + WA_off[l];
        a.W[1] = W[l][2]; a.T[1] = wt + WA_off[l] + (size_t)512 * K;
        a.W[2] = W[l][1]; a.T[2] = wt + WB_off[l];
        a.W[3] = W[l][3]; a.T[3] = wt + WB_off[l] + (size_t)512 * K;
        a.W[4] = W[l][4]; a.T[4] = wt + WB_off[l] + (size_t)1024 * K;
        wt_batch<<<dim3(K / 32, KH / 32, 5), dim3(32, 8)>>>(a, K);
    };
    auto mkrel = [&](int rel) {
        RelSrc R;
        R.rp   = rp + rel * RPN;
        R.colv = colv + eoff[rel];
        R.valv = valv + eoff[rel];
        switch (rel) {
            case 0: R.x = tmpA;         R.ldx = 1024; break;
            case 1: R.x = tmpB;         R.ldx = 1536; break;
            case 2: R.x = tmpA + 512;   R.ldx = 1024; break;
            case 3: R.x = tmpB + 512;   R.ldx = 1536; break;
            default: R.x = tmpB + 1024; R.ldx = 1536; break;
        }
        return R;
    };
    auto round_to = [&](const float* s, float* d, size_t nelem) {
        size_t n4 = nelem / 4;
        tf32_round4<<<(unsigned)((n4 + 255) / 256), 256>>>(s, d, n4);
    };

    // Launch order: #4 is the big fused M=30000/N=1024/K=1024 gemm (profiled).
    wt_layer(0);                                      // 1
    round_to(feat0, f0t, (size_t)KN0 * KF);           // 2
    round_to(feat1, f1t, (size_t)KN1 * KF);           // 3
    gemm(f0t, wt + WA_off[0], tmpA, KN0, 1024, KF);   // 4  <- profiled
    gemm(f1t, wt + WB_off[0], tmpB, KN1, 1536, KF);   // 5

    // ---- batched CSR build (5 launches) ----
    {
        CsrArgs ca;
        for (int r = 0; r < 5; r++) {
            ca.row[r] = a_row[r]; ca.col[r] = a_col[r]; ca.val[r] = a_val[r];
            ca.E[r] = Ecnt[r]; ca.eoff[r] = (long long)eoff[r];
        }
        seti<<<(5 * RPN + 255) / 256, 256>>>(wp, 5 * RPN, 0);
        hist_b<<<dim3((maxE + 255) / 256, 1, 5), 256>>>(ca, wp);
        exscan_b<<<5, 1024>>>(wp, rp);
        copyi<<<(5 * RPN + 255) / 256, 256>>>(rp, wp, 5 * RPN);
        scatter_b<<<dim3((maxE + 255) / 256, 1, 5), 256>>>(ca, wp, colv, valv);
    }

    RelSrc dummy{};

    // ---------------- Layer 1 ----------------
    spmm_multi<1, 2><<<(KN0 * 32 + 255) / 256, 256>>>(
        mkrel(0), mkrel(1), dummy, e00t, out, KN0, 0);
    spmm_multi<1, 3><<<(KN1 * 32 + 255) / 256, 256>>>(
        mkrel(2), mkrel(3), mkrel(4), e01t, out + (size_t)KN0 * LDO, KN1, 0);

    wt_layer(1);
    wt_layer(2);

    // ---------------- Layer 2 ----------------
    gemm(e00t, wt + WA_off[1], tmpA, KN0, 1024, KH);
    gemm(e01t, wt + WB_off[1], tmpB, KN1, 1536, KH);
    spmm_multi<2, 2><<<(KN0 * 32 + 255) / 256, 256>>>(
        mkrel(0), mkrel(1), dummy, e20t, nullptr, KN0, 0);
    spmm_multi<2, 3><<<(KN1 * 32 + 255) / 256, 256>>>(
        mkrel(2), mkrel(3), mkrel(4), e21t, nullptr, KN1, 0);

    // ---------------- Layer 3 ----------------
    gemm(e20t, wt + WA_off[2], tmpA, KN0, 1024, KH);
    gemm(e21t, wt + WB_off[2], tmpB, KN1, 1536, KH);
    spmm_multi<0, 2><<<(KN0 * 32 + 255) / 256, 256>>>(
        mkrel(0), mkrel(1), dummy, out + 1024, nullptr, KN0, LDO);
    spmm_multi<0, 3><<<(KN1 * 32 + 255) / 256, 256>>>(
        mkrel(2), mkrel(3), mkrel(4), out + (size_t)KN0 * LDO + 1024, nullptr, KN1, LDO);
}

// round 16
// speedup vs baseline: 1.0653x; 1.0653x over previous
#include <cuda_runtime.h>
#include <cuda_bf16.h>
#include <cstdint>
#include <cstddef>

// ============================================================================
// DecagonModel — R16: R14 GEMM (BK=32, 2 CTA/SM — best known) + R15's batched
// preprocessing (wt 15->3 launches, CSR build 25->5).
// ============================================================================

#define KN0 30000
#define KN1 6000
#define KF  1024
#define KH  512
#define LDO 1536
#define ECAP 2100000
#define RPN  30001

// ---------------- device-global scratch -------------------------------------
__device__ float g_tmpA[KN0 * 1024];
__device__ float g_tmpB[KN1 * 1536];

__device__ float g_f0t[KN0 * KF];
__device__ float g_f1t[KN1 * KF];
__device__ float g_e00t[KN0 * KH];
__device__ float g_e01t[KN1 * KH];
__device__ float g_e20t[KN0 * KH];
__device__ float g_e21t[KN1 * KH];

#define WT_TOTAL 5242880
__device__ float g_wt[WT_TOTAL];

__device__ int   g_rp[5 * RPN];
__device__ int   g_wp[5 * RPN];
__device__ int   g_colv[ECAP];
__device__ float g_valv[ECAP];

// ---------------- helpers ---------------------------------------------------
__device__ __forceinline__ uint32_t smem_u32(const void* p) {
    uint32_t a;
    asm("{ .reg .u64 t; cvta.to.shared.u64 t, %1; cvt.u32.u64 %0, t; }"
        : "=r"(a) : "l"(p));
    return a;
}
__device__ __forceinline__ void cpa16(uint32_t dst, const void* src, bool v) {
    asm volatile("cp.async.cg.shared.global [%0], [%1], 16, %2;"
                 :: "r"(dst), "l"(src), "r"(v ? 16 : 0) : "memory");
}
__device__ __forceinline__ void ldsm4(uint32_t& r0, uint32_t& r1, uint32_t& r2,
                                      uint32_t& r3, uint32_t addr) {
    asm volatile("ldmatrix.sync.aligned.m8n8.x4.shared.b16 {%0,%1,%2,%3}, [%4];"
                 : "=r"(r0), "=r"(r1), "=r"(r2), "=r"(r3) : "r"(addr));
}
__device__ __forceinline__ void mma_tf32(float& c0, float& c1, float& c2, float& c3,
                                         uint32_t a0, uint32_t a1, uint32_t a2, uint32_t a3,
                                         uint32_t b0, uint32_t b1) {
    asm volatile(
        "mma.sync.aligned.m16n8k8.row.col.f32.tf32.tf32.f32 "
        "{%0,%1,%2,%3}, {%4,%5,%6,%7}, {%8,%9}, {%0,%1,%2,%3};"
        : "+f"(c0), "+f"(c1), "+f"(c2), "+f"(c3)
        : "r"(a0), "r"(a1), "r"(a2), "r"(a3), "r"(b0), "r"(b1));
}
__device__ __forceinline__ float tf32r(float x) {
    uint32_t r;
    asm("cvt.rna.tf32.f32 %0, %1;" : "=r"(r) : "f"(x));
    return __uint_as_float(r);
}

// ----------------------------------------------------------------------------
// TF32 GEMM (R12/R14 mainloop — BK=32, 3-stage, fragment double-buffering)
// ----------------------------------------------------------------------------
#define STG_BYTES 32768u
#define GEMM_SMEM (3 * STG_BYTES)

__global__ __launch_bounds__(256) void gemm_tf32(
    const float* __restrict__ A, const float* __restrict__ B,
    float* __restrict__ C, int M, int N, int K)
{
    extern __shared__ char dyn_smem[];
    const uint32_t sbase = smem_u32(dyn_smem);

    const int tid  = threadIdx.x;
    const int wid  = tid >> 5;
    const int lane = tid & 31;
    const int bm   = blockIdx.y * 128;
    const int bn   = blockIdx.x * 128;
    const int wm   = (wid & 1) * 64;
    const int wn   = (wid >> 1) * 32;

    const int NC = K >> 5;

    const int r0 = tid >> 3, cs = tid & 7;
    const uint32_t d0 = (uint32_t)(r0 * 128 + ((cs * 16) ^ ((r0 & 7) << 4)));
    const float* pA[4]; const float* pB[4]; bool vA[4];
#pragma unroll
    for (int it = 0; it < 4; it++) {
        int r  = r0 + 32 * it;
        int gr = bm + r;
        vA[it] = gr < M;
        pA[it] = A + (size_t)(vA[it] ? gr : 0) * K + cs * 4;
        pB[it] = B + (size_t)(bn + r) * K + cs * 4;
    }

    const int mi  = lane >> 3;
    const int r8  = lane & 7;
    const int aro = (mi & 1) * 8 + r8;
    const int akb = (mi >> 1) * 16;
    uint32_t offA[4], offB[2];
#pragma unroll
    for (int i = 0; i < 4; i++) {
        int r = wm + i * 16 + aro;
        offA[i] = (uint32_t)(r * 128 + (akb ^ ((r & 7) << 4)));
    }
#pragma unroll
    for (int j2 = 0; j2 < 2; j2++) {
        int r = wn + j2 * 16 + aro;
        offB[j2] = (uint32_t)(16384 + r * 128 + (akb ^ ((r & 7) << 4)));
    }

    float acc[4][4][4];
#pragma unroll
    for (int i = 0; i < 4; i++)
#pragma unroll
        for (int j = 0; j < 4; j++)
#pragma unroll
            for (int q = 0; q < 4; q++) acc[i][j][q] = 0.f;

    auto load_chunk = [&](uint32_t stW) {
        const uint32_t dA = sbase + stW + d0;
#pragma unroll
        for (int it = 0; it < 4; it++) {
            cpa16(dA + 4096u * it,          pA[it], vA[it]);
            cpa16(dA + 16384u + 4096u * it, pB[it], true);
            pA[it] += 32; pB[it] += 32;
        }
        asm volatile("cp.async.commit_group;" ::: "memory");
    };

    uint32_t stW = 0, stR = 0;
    load_chunk(stW); stW = STG_BYTES;
    load_chunk(stW); stW = 2 * STG_BYTES;

    uint32_t fa[2][4][4], fb[2][4][2];

    auto load_frags = [&](uint32_t st, uint32_t kb, int buf) {
#pragma unroll
        for (int i = 0; i < 4; i++)
            ldsm4(fa[buf][i][0], fa[buf][i][1], fa[buf][i][2], fa[buf][i][3],
                  st + (offA[i] ^ kb));
#pragma unroll
        for (int j2 = 0; j2 < 2; j2++) {
            uint32_t q0, q1, q2, q3;
            ldsm4(q0, q1, q2, q3, st + (offB[j2] ^ kb));
            fb[buf][j2 * 2][0]     = q0; fb[buf][j2 * 2][1]     = q2;
            fb[buf][j2 * 2 + 1][0] = q1; fb[buf][j2 * 2 + 1][1] = q3;
        }
    };
    auto do_mmas = [&](int buf) {
#pragma unroll
        for (int i = 0; i < 4; i++)
#pragma unroll
            for (int j = 0; j < 4; j++)
                mma_tf32(acc[i][j][0], acc[i][j][1], acc[i][j][2], acc[i][j][3],
                         fa[buf][i][0], fa[buf][i][1], fa[buf][i][2], fa[buf][i][3],
                         fb[buf][j][0], fb[buf][j][1]);
    };

    for (int c = 0; c < NC; c++) {
        asm volatile("cp.async.wait_group 1;" ::: "memory");
        __syncthreads();
        if (c + 2 < NC) {
            load_chunk(stW);
            stW += STG_BYTES; if (stW == 3 * STG_BYTES) stW = 0;
        }

        const uint32_t st = sbase + stR;
        stR += STG_BYTES; if (stR == 3 * STG_BYTES) stR = 0;

        load_frags(st, 0, 0);
#pragma unroll
        for (int s = 0; s < 4; s++) {
            if (s < 3) load_frags(st, (uint32_t)(32 * (s + 1)), (s + 1) & 1);
            do_mmas(s & 1);
        }
    }

    const int lm = lane >> 2, ln = (lane & 3) * 2;
#pragma unroll
    for (int i = 0; i < 4; i++) {
#pragma unroll
        for (int j = 0; j < 4; j++) {
            int m0 = bm + wm + i * 16 + lm;
            int n0 = bn + wn + j * 8 + ln;
            if (m0 < M)
                *(float2*)(C + (size_t)m0 * N + n0) =
                    make_float2(acc[i][j][0], acc[i][j][1]);
            if (m0 + 8 < M)
                *(float2*)(C + (size_t)(m0 + 8) * N + n0) =
                    make_float2(acc[i][j][2], acc[i][j][3]);
        }
    }
}

// ----------------------------------------------------------------------------
// Batched CSR build
// ----------------------------------------------------------------------------
struct CsrArgs {
    const int*   row[5];
    const int*   col[5];
    const float* val[5];
    int          E[5];
    long long    eoff[5];
};

__global__ void seti(int* __restrict__ p, int n, int v)
{
    int i = blockIdx.x * blockDim.x + threadIdx.x;
    if (i < n) p[i] = v;
}
__global__ void hist_b(CsrArgs a, int* __restrict__ wp)
{
    int z = blockIdx.z;
    int i = blockIdx.x * blockDim.x + threadIdx.x;
    if (i < a.E[z]) atomicAdd(&wp[z * RPN + a.row[z][i]], 1);
}
__global__ void exscan_b(const int* __restrict__ cnt_all, int* __restrict__ rp_all)
{
    __shared__ int part[1024];
    const int z = blockIdx.x;
    const int n = (z < 2) ? KN0 : KN1;
    const int* cnt = cnt_all + z * RPN;
    int* rp = rp_all + z * RPN;
    const int t = threadIdx.x;
    const int chunk = (n + 1 + 1023) / 1024;
    const int base = t * chunk;
    int s = 0;
    for (int i = 0; i < chunk; i++) {
        int idx = base + i;
        if (idx < n) s += cnt[idx];
    }
    part[t] = s;
    __syncthreads();
    for (int off = 1; off < 1024; off <<= 1) {
        int v = (t >= off) ? part[t - off] : 0;
        __syncthreads();
        part[t] += v;
        __syncthreads();
    }
    int run = part[t] - s;
    for (int i = 0; i < chunk; i++) {
        int idx = base + i;
        if (idx <= n) {
            rp[idx] = run;
            if (idx < n) run += cnt[idx];
        }
    }
}
__global__ void copyi(const int* __restrict__ s, int* __restrict__ d, int n)
{
    int i = blockIdx.x * blockDim.x + threadIdx.x;
    if (i < n) d[i] = s[i];
}
__global__ void scatter_b(CsrArgs a, int* __restrict__ wp,
                          int* __restrict__ colv, float* __restrict__ valv)
{
    int z = blockIdx.z;
    int i = blockIdx.x * blockDim.x + threadIdx.x;
    if (i >= a.E[z]) return;
    int p = atomicAdd(&wp[z * RPN + a.row[z][i]], 1);
    colv[a.eoff[z] + p] = a.col[z][i];
    valv[a.eoff[z] + p] = a.val[z][i];
}

// ----------------------------------------------------------------------------
// Multi-relation SpMM
// ----------------------------------------------------------------------------
struct RelSrc {
    const int*   rp;
    const int*   colv;
    const float* valv;
    const float* x;
    int          ldx;
};

__device__ __forceinline__ void spmm_acc(
    const RelSrc& R, int row, int lane,
    float4& a0, float4& a1, float4& a2, float4& a3)
{
    int s = __ldg(&R.rp[row]), e = __ldg(&R.rp[row + 1]);
#pragma unroll 2
    for (int i = s; i < e; i++) {
        int   c = __ldg(&R.colv[i]);
        float v = __ldg(&R.valv[i]);
        const float4* xr = reinterpret_cast<const float4*>(R.x + (size_t)c * R.ldx);
        float4 t;
        t = xr[lane];
        a0.x = fmaf(v, t.x, a0.x); a0.y = fmaf(v, t.y, a0.y);
        a0.z = fmaf(v, t.z, a0.z); a0.w = fmaf(v, t.w, a0.w);
        t = xr[lane + 32];
        a1.x = fmaf(v, t.x, a1.x); a1.y = fmaf(v, t.y, a1.y);
        a1.z = fmaf(v, t.z, a1.z); a1.w = fmaf(v, t.w, a1.w);
        t = xr[lane + 64];
        a2.x = fmaf(v, t.x, a2.x); a2.y = fmaf(v, t.y, a2.y);
        a2.z = fmaf(v, t.z, a2.z); a2.w = fmaf(v, t.w, a2.w);
        t = xr[lane + 96];
        a3.x = fmaf(v, t.x, a3.x); a3.y = fmaf(v, t.y, a3.y);
        a3.z = fmaf(v, t.z, a3.z); a3.w = fmaf(v, t.w, a3.w);
    }
}

template <int MODE, int NREL>
__global__ __launch_bounds__(256) void spmm_multi(
    RelSrc r0, RelSrc r1, RelSrc r2,
    float* __restrict__ dst, float* __restrict__ out2, int nrows, int ldo)
{
    int row  = (blockIdx.x * blockDim.x + threadIdx.x) >> 5;
    int lane = threadIdx.x & 31;
    if (row >= nrows) return;

    float4 a0 = make_float4(0.f, 0.f, 0.f, 0.f), a1 = a0, a2 = a0, a3 = a0;
    spmm_acc(r0, row, lane, a0, a1, a2, a3);
    if (NREL >= 2) spmm_acc(r1, row, lane, a0, a1, a2, a3);
    if (NREL >= 3) spmm_acc(r2, row, lane, a0, a1, a2, a3);

    if (MODE == 0) {
        float4* o = reinterpret_cast<float4*>(dst + (size_t)row * ldo);
        o[lane] = a0; o[lane + 32] = a1; o[lane + 64] = a2; o[lane + 96] = a3;
        return;
    }

    a0.x = fmaxf(a0.x, 0.f); a0.y = fmaxf(a0.y, 0.f); a0.z = fmaxf(a0.z, 0.f); a0.w = fmaxf(a0.w, 0.f);
    a1.x = fmaxf(a1.x, 0.f); a1.y = fmaxf(a1.y, 0.f); a1.z = fmaxf(a1.z, 0.f); a1.w = fmaxf(a1.w, 0.f);
    a2.x = fmaxf(a2.x, 0.f); a2.y = fmaxf(a2.y, 0.f); a2.z = fmaxf(a2.z, 0.f); a2.w = fmaxf(a2.w, 0.f);
    a3.x = fmaxf(a3.x, 0.f); a3.y = fmaxf(a3.y, 0.f); a3.z = fmaxf(a3.z, 0.f); a3.w = fmaxf(a3.w, 0.f);

    if (MODE == 1) {
        float4* o = reinterpret_cast<float4*>(out2 + (size_t)row * LDO);
        o[lane]       = a0; o[lane + 32]  = a1; o[lane + 64]  = a2; o[lane + 96]  = a3;
        o[lane + 128] = a0; o[lane + 160] = a1; o[lane + 192] = a2; o[lane + 224] = a3;
    }

    a0.x = tf32r(a0.x); a0.y = tf32r(a0.y); a0.z = tf32r(a0.z); a0.w = tf32r(a0.w);
    a1.x = tf32r(a1.x); a1.y = tf32r(a1.y); a1.z = tf32r(a1.z); a1.w = tf32r(a1.w);
    a2.x = tf32r(a2.x); a2.y = tf32r(a2.y); a2.z = tf32r(a2.z); a2.w = tf32r(a2.w);
    a3.x = tf32r(a3.x); a3.y = tf32r(a3.y); a3.z = tf32r(a3.z); a3.w = tf32r(a3.w);
    float4* p = reinterpret_cast<float4*>(dst + (size_t)row * KH);
    p[lane] = a0; p[lane + 32] = a1; p[lane + 64] = a2; p[lane + 96] = a3;
}

// ----------------------------------------------------------------------------
// Converters
// ----------------------------------------------------------------------------
__global__ void tf32_round4(const float* __restrict__ x, float* __restrict__ y, size_t n4)
{
    size_t i = blockIdx.x * (size_t)blockDim.x + threadIdx.x;
    if (i >= n4) return;
    float4 t = reinterpret_cast<const float4*>(x)[i];
    t.x = tf32r(t.x); t.y = tf32r(t.y); t.z = tf32r(t.z); t.w = tf32r(t.w);
    reinterpret_cast<float4*>(y)[i] = t;
}

struct WtArgs { const float* W[5]; float* T[5]; };

__global__ void wt_batch(WtArgs a, int K)
{
    const int z = blockIdx.z;
    const float* W = a.W[z];
    float* T = a.T[z];
    __shared__ float t[32][33];
    int kb = blockIdx.x * 32, nb = blockIdx.y * 32;
    int x = threadIdx.x, y = threadIdx.y;
#pragma unroll
    for (int i = 0; i < 32; i += 8)
        t[y + i][x] = W[(size_t)(kb + y + i) * KH + nb + x];
    __syncthreads();
#pragma unroll
    for (int i = 0; i < 32; i += 8)
        T[(size_t)(nb + y + i) * K + kb + x] = tf32r(t[x][y + i]);
}

// ----------------------------------------------------------------------------
// Host orchestration
// ----------------------------------------------------------------------------
extern "C" void kernel_launch(void* const* d_in, const int* in_sizes, int n_in,
                              void* d_out, int out_size)
{
    const float* feat0 = (const float*)d_in[0];
    const float* feat1 = (const float*)d_in[1];

    const int*   a_row[5]; const int* a_col[5]; const float* a_val[5]; int Ecnt[5];
    for (int i = 0; i < 5; i++) {
        a_row[i] = (const int*)d_in[2 + 3 * i];
        a_col[i] = (const int*)d_in[3 + 3 * i];
        a_val[i] = (const float*)d_in[4 + 3 * i];
        Ecnt[i]  = in_sizes[2 + 3 * i];
    }
    const float* W[3][5];
    for (int r = 0; r < 5; r++)
        for (int l = 0; l < 3; l++)
            W[l][r] = (const float*)d_in[17 + 3 * r + l];

    float *tmpA, *tmpB;
    float *f0t, *f1t, *e00t, *e01t, *e20t, *e21t, *wt;
    int *rp, *wp, *colv; float *valv;
    {
        void* p;
        cudaGetSymbolAddress(&p, g_tmpA); tmpA = (float*)p;
        cudaGetSymbolAddress(&p, g_tmpB); tmpB = (float*)p;
        cudaGetSymbolAddress(&p, g_f0t);  f0t  = (float*)p;
        cudaGetSymbolAddress(&p, g_f1t);  f1t  = (float*)p;
        cudaGetSymbolAddress(&p, g_e00t); e00t = (float*)p;
        cudaGetSymbolAddress(&p, g_e01t); e01t = (float*)p;
        cudaGetSymbolAddress(&p, g_e20t); e20t = (float*)p;
        cudaGetSymbolAddress(&p, g_e21t); e21t = (float*)p;
        cudaGetSymbolAddress(&p, g_wt);   wt   = (float*)p;
        cudaGetSymbolAddress(&p, g_rp);   rp   = (int*)p;
        cudaGetSymbolAddress(&p, g_wp);   wp   = (int*)p;
        cudaGetSymbolAddress(&p, g_colv); colv = (int*)p;
        cudaGetSymbolAddress(&p, g_valv); valv = (float*)p;
    }
    float* out = (float*)d_out;

    const size_t WA_off[3] = {0, 2621440, 3932160};
    const size_t WB_off[3] = {1048576, 3145728, 4456448};
    const int    Kl[3]     = {KF, KH, KH};

    size_t eoff[5]; size_t acc_e = 0;
    for (int r = 0; r < 5; r++) { eoff[r] = acc_e; acc_e += (size_t)Ecnt[r]; }
    int maxE = 0;
    for (int r = 0; r < 5; r++) if (Ecnt[r] > maxE) maxE = Ecnt[r];

    cudaFuncSetAttribute(gemm_tf32, cudaFuncAttributeMaxDynamicSharedMemorySize, GEMM_SMEM);

    auto gemm = [&](const float* A, const float* B, float* C, int M, int N, int K) {
        dim3 grid(N / 128, (M + 127) / 128);
        gemm_tf32<<<grid, 256, GEMM_SMEM>>>(A, B, C, M, N, K);
    };
    auto wt_layer = [&](int l) {
        int K = Kl[l];
        WtArgs a;
        a.W[0] = W[l][0]; a.T[0] = wt + WA_off[l];
        a.W[1] = W[l][2]; a.T[1] = wt + WA_off[l] + (size_t)512 * K;
        a.W[2] = W[l][1]; a.T[2] = wt + WB_off[l];
        a.W[3] = W[l][3]; a.T[3] = wt + WB_off[l] + (size_t)512 * K;
        a.W[4] = W[l][4]; a.T[4] = wt + WB_off[l] + (size_t)1024 * K;
        wt_batch<<<dim3(K / 32, KH / 32, 5), dim3(32, 8)>>>(a, K);
    };
    auto mkrel = [&](int rel) {
        RelSrc R;
        R.rp   = rp + rel * RPN;
        R.colv = colv + eoff[rel];
        R.valv = valv + eoff[rel];
        switch (rel) {
            case 0: R.x = tmpA;         R.ldx = 1024; break;
            case 1: R.x = tmpB;         R.ldx = 1536; break;
            case 2: R.x = tmpA + 512;   R.ldx = 1024; break;
            case 3: R.x = tmpB + 512;   R.ldx = 1536; break;
            default: R.x = tmpB + 1024; R.ldx = 1536; break;
        }
        return R;
    };
    auto round_to = [&](const float* s, float* d, size_t nelem) {
        size_t n4 = nelem / 4;
        tf32_round4<<<(unsigned)((n4 + 255) / 256), 256>>>(s, d, n4);
    };

    // Launch order: #4 is the big fused M=30000/N=1024/K=1024 gemm (profiled).
    wt_layer(0);                                      // 1
    round_to(feat0, f0t, (size_t)KN0 * KF);           // 2
    round_to(feat1, f1t, (size_t)KN1 * KF);           // 3
    gemm(f0t, wt + WA_off[0], tmpA, KN0, 1024, KF);   // 4  <- profiled
    gemm(f1t, wt + WB_off[0], tmpB, KN1, 1536, KF);   // 5

    // ---- batched CSR build (5 launches) ----
    {
        CsrArgs ca;
        for (int r = 0; r < 5; r++) {
            ca.row[r] = a_row[r]; ca.col[r] = a_col[r]; ca.val[r] = a_val[r];
            ca.E[r] = Ecnt[r]; ca.eoff[r] = (long long)eoff[r];
        }
        seti<<<(5 * RPN + 255) / 256, 256>>>(wp, 5 * RPN, 0);
        hist_b<<<dim3((maxE + 255) / 256, 1, 5), 256>>>(ca, wp);
        exscan_b<<<5, 1024>>>(wp, rp);
        copyi<<<(5 * RPN + 255) / 256, 256>>>(rp, wp, 5 * RPN);
        scatter_b<<<dim3((maxE + 255) / 256, 1, 5), 256>>>(ca, wp, colv, valv);
    }

    RelSrc dummy{};

    // ---------------- Layer 1 ----------------
    spmm_multi<1, 2><<<(KN0 * 32 + 255) / 256, 256>>>(
        mkrel(0), mkrel(1), dummy, e00t, out, KN0, 0);
    spmm_multi<1, 3><<<(KN1 * 32 + 255) / 256, 256>>>(
        mkrel(2), mkrel(3), mkrel(4), e01t, out + (size_t)KN0 * LDO, KN1, 0);

    wt_layer(1);
    wt_layer(2);

    // ---------------- Layer 2 ----------------
    gemm(e00t, wt + WA_off[1], tmpA, KN0, 1024, KH);
    gemm(e01t, wt + WB_off[1], tmpB, KN1, 1536, KH);
    spmm_multi<2, 2><<<(KN0 * 32 + 255) / 256, 256>>>(
        mkrel(0), mkrel(1), dummy, e20t, nullptr, KN0, 0);
    spmm_multi<2, 3><<<(KN1 * 32 + 255) / 256, 256>>>(
        mkrel(2), mkrel(3), mkrel(4), e21t, nullptr, KN1, 0);

    // ---------------- Layer 3 ----------------
    gemm(e20t, wt + WA_off[2], tmpA, KN0, 1024, KH);
    gemm(e21t, wt + WB_off[2], tmpB, KN1, 1536, KH);
    spmm_multi<0, 2><<<(KN0 * 32 + 255) / 256, 256>>>(
        mkrel(0), mkrel(1), dummy, out + 1024, nullptr, KN0, LDO);
    spmm_multi<0, 3><<<(KN1 * 32 + 255) / 256, 256>>>(
        mkrel(2), mkrel(3), mkrel(4), out + (size_t)KN0 * LDO + 1024, nullptr, KN1, LDO);
}